// round 14
// baseline (speedup 1.0000x reference)
#include <cuda_runtime.h>

// EdgeBlock fused, scatter-form value path. B=4, L=1024, N=16, D=64, W=16, V=33.
//
// R14 key idea: invert the value GATHER into a SCATTER. Each source row r
// serves exactly 33 output rows (out[r][0..16] and out[(r-k)%L][16+k]), all
// contiguous 4KB segments. A 256-thread CTA = one full row (256 float4), so:
// 1 LDG.128 -> register -> 33x STG.128. This deletes ALL smem staging, LDS,
// STS and __syncthreads from the value path; chip-wide hidden reads drop to
// the optimal 16 MB; value smem = 0 so the fused launch needs only the score
// path's 63 KB -> 3 CTAs/SM (was 2 at 96 KB).
//
// Outputs (concatenated fp32 in d_out):
//   window_score (B,N,L,V)   = 2,162,688 floats
//   value_h      (B,L,V,N,D) = 138,412,032 floats (553 MB, DRAM-write bound)

#define Lc 1024
#define MASK_FILL -1e12f

__global__ void __launch_bounds__(256, 3) fused_kernel(
    const float* __restrict__ hidden,
    const int*   __restrict__ mask,
    const float* __restrict__ upon,
    const float* __restrict__ down,
    const float* __restrict__ cross,
    float*       __restrict__ out_ws,
    float4*      __restrict__ out_val)
{
    extern __shared__ float sm[];
    const int t   = threadIdx.x;
    const int bid = blockIdx.x;
    const int s   = bid >> 1;               // 0..511 within each class

    if ((bid & 1) == 0) {
        // -------- value path (scatter): 8 source rows, no smem, no barriers ----
        const float4* hidden4 = (const float4*)hidden;
        const int b  = s >> 7;               // 0..3
        const int r0 = (s & 127) * 8;        // first source row

        float4 vals[8];
#pragma unroll
        for (int rr = 0; rr < 8; ++rr)
            vals[rr] = __ldg(&hidden4[((size_t)((b << 10) + r0 + rr)) * 256 + t]);

#pragma unroll
        for (int rr = 0; rr < 8; ++rr) {
            const int r = r0 + rr;
            // out[l=r][v=0..16] : 17 contiguous 4KB rows
            size_t lbase = ((size_t)((b << 10) + r)) * 33 * 256 + t;
#pragma unroll
            for (int v = 0; v <= 16; ++v)
                __stcs(&out_val[lbase + (size_t)v * 256], vals[rr]);
            // out[l=(r-k)%L][v=16+k], k=1..16
#pragma unroll
            for (int k = 1; k <= 16; ++k) {
                int l = (r - k) & (Lc - 1);
                __stcs(&out_val[(((size_t)((b << 10) + l)) * 33 + 16 + k) * 256 + t],
                       vals[rr]);
            }
        }
        return;
    }

    // ------------------------- score path: s in 0..511 -------------------------
    // (verbatim from R13 — passing at 6.1e-16)
    const int tile = s & 7, n = (s >> 3) & 15, b = s >> 7;
    const int l0 = tile * 128;

    float* shC  = sm;             // [64][68]  (cross transposed: shC[h*68+d])
    float* shH  = sm + 4352;      // [160][68] (rows l0-16 .. l0+143, wrapped)
    float* su   = sm + 15232;     // [160]
    float* sd   = sm + 15392;     // [160]
    float* shup = sm + 15552;     // [64]
    float* shdn = sm + 15616;     // [64]
    int*   shm  = (int*)(sm + 15680); // [160]
    // 15840 floats = 63,360 B -> 3 CTAs/SM

    for (int i = t; i < 4096; i += 256) {
        int d2 = i >> 6, h2 = i & 63;
        shC[h2 * 68 + d2] = cross[n * 4096 + i];
    }
    if (t < 64) { shup[t] = upon[n * 64 + t]; shdn[t] = down[n * 64 + t]; }

    {
        const float4* h4 = (const float4*)hidden;
        for (int i = t; i < 2560; i += 256) {         // 160 rows * 16 quads
            int rr = i >> 4, dq = i & 15;
            int row = (l0 - 16 + rr) & (Lc - 1);
            float4 v = h4[(((size_t)(b << 10) + row) * 16 + n) * 16 + dq];
            *(float4*)&shH[rr * 68 + dq * 4] = v;
        }
    }
    if (t < 160) shm[t] = mask[(b << 10) + ((l0 + t) & (Lc - 1))];
    __syncthreads();

    if (t < 160) {
        const float* hr = &shH[t * 68];
        float a = 0.f, c = 0.f;
#pragma unroll
        for (int dq = 0; dq < 16; ++dq) {
            float4 hv = *(const float4*)&hr[dq * 4];
            float4 up = *(const float4*)&shup[dq * 4];
            float4 dn = *(const float4*)&shdn[dq * 4];
            a += hv.x * up.x + hv.y * up.y + hv.z * up.z + hv.w * up.w;
            c += hv.x * dn.x + hv.y * dn.y + hv.z * dn.z + hv.w * dn.w;
        }
        su[t] = a; sd[t] = c;
    }
    __syncthreads();

    const int w = t >> 5, lane = t & 31;

    for (int g = 0; g < 2; ++g) {
        const int lloc0 = w * 16 + g * 8;   // 8 consecutive l's per group
        const int rb    = lloc0 + 16;       // shH row of first l

        // Phase A: qc[i][h] for 8 l's; lane owns h=lane, h=lane+32.
        float a0[8] = {0,0,0,0,0,0,0,0}, a1[8] = {0,0,0,0,0,0,0,0};
#pragma unroll
        for (int dq = 0; dq < 16; ++dq) {
            float4 c0 = *(const float4*)&shC[lane * 68 + dq * 4];
            float4 c1 = *(const float4*)&shC[(lane + 32) * 68 + dq * 4];
#pragma unroll
            for (int i = 0; i < 8; ++i) {
                float4 hd = *(const float4*)&shH[(rb + i) * 68 + dq * 4];
                a0[i] += hd.x * c0.x + hd.y * c0.y + hd.z * c0.z + hd.w * c0.w;
                a1[i] += hd.x * c1.x + hd.y * c1.y + hd.z * c1.z + hd.w * c1.w;
            }
        }

        // Phase B: 17 window products per l via shuffle reduction.
        float pk[8];
#pragma unroll
        for (int i = 0; i < 8; ++i) {
            pk[i] = 0.f;
            for (int o = 0; o < 17; ++o) {
                const float* hr = &shH[(rb + i + o) * 68];
                float p = a0[i] * hr[lane] + a1[i] * hr[lane + 32];
#pragma unroll
                for (int d2 = 16; d2 > 0; d2 >>= 1)
                    p += __shfl_xor_sync(0xffffffffu, p, d2);
                if (lane == o) pk[i] = p;
            }
        }

        // Assembly: 33 scores per l.
#pragma unroll
        for (int i = 0; i < 8; ++i) {
            const int lloc = lloc0 + i, l = l0 + lloc, rbl = rb + i;
            size_t ob = ((size_t)((b * 16 + n) * Lc + l)) * 33;

            {
                int v = lane;
                int offu = (v <= 16) ? 0 : (v - 16);
                int offd = (v <  16) ? (v - 16) : 0;
                float prod = __shfl_sync(0xffffffffu, pk[i], offu);
                float sc = prod + su[rbl + offu] + sd[rbl + offd];
                sc = (sc > 0.f) ? sc : 5.0f * sc;           // leaky_relu slope 5
                bool m = (l + offd >= 0) && (l + offu < Lc) &&
                         (shm[lloc + offu] != 0);
                __stcs(&out_ws[ob + v], m ? sc : MASK_FILL);
            }
            {
                float prod32 = __shfl_sync(0xffffffffu, pk[i], 16);
                if (lane == 0) {
                    float sc = prod32 + su[rbl + 16] + sd[rbl];
                    sc = (sc > 0.f) ? sc : 5.0f * sc;
                    bool m = (l + 16 < Lc) && (shm[lloc + 16] != 0);
                    __stcs(&out_ws[ob + 32], m ? sc : MASK_FILL);
                }
            }
        }
    }
}

extern "C" void kernel_launch(void* const* d_in, const int* in_sizes, int n_in,
                              void* d_out, int out_size) {
    const float* hidden = (const float*)d_in[0];
    const int*   mask   = (const int*)d_in[1];      // bool -> int32 on the wire
    const float* upon   = (const float*)d_in[2];
    const float* down   = (const float*)d_in[3];
    const float* cross  = (const float*)d_in[4];
    // d_in[5] (window_size) fixed at 16; compiled in.

    float*  out_ws  = (float*)d_out;
    float4* out_val = (float4*)(out_ws + (size_t)4 * 16 * Lc * 33); // 2,162,688 floats

    const int smem = 15840 * (int)sizeof(float);    // 63,360 B -> 3 CTAs/SM
    cudaFuncSetAttribute(fused_kernel, cudaFuncAttributeMaxDynamicSharedMemorySize, smem);

    // 1024 blocks, 1:1 interleave: even bid = value (scatter), odd bid = score.
    fused_kernel<<<1024, 256, smem>>>(hidden, mask, upon, down, cross,
                                      out_ws, out_val);
}